// round 14
// baseline (speedup 1.0000x reference)
#include <cuda_runtime.h>
#include <cuda_bf16.h>
#include <math.h>
#include <stdint.h>

// Problem constants
#define BB 8
#define SS 4096
#define DD 1024
#define MMm 32
#define KKk 3
#define RRr 64
#define NROWS 32768           // BB*SS
#define NELEM ((size_t)NROWS*DD)

// ---------------- scratch (static __device__ globals; no allocation) ----------------
__device__ float g_scores[NROWS];
__device__ int   g_aidx[BB*KKk];
__device__ float g_apos[BB*KKk];
__device__ float g_Zs[BB*KKk];
__device__ float g_transl[BB*KKk*DD];
__device__ float g_gate[NROWS];
__device__ float g_lb[NROWS];
__device__ float g_tsaug[33554432];          // fp32 (mode-1 epilogue base; accuracy-critical)
// bf16 operands / intermediates
__device__ __nv_bfloat16 gb_tsn[33554432];
__device__ __nv_bfloat16 gb_ptn[33554432];
__device__ __nv_bfloat16 gb_shared[33554432];  // mode-0 output (bf16)
__device__ __nv_bfloat16 gb_d1[33554432];      // pooled - tsn
__device__ __nv_bfloat16 gb_d2[33554432];      // pooled - ptn
__device__ __nv_bfloat16 g_Wb_sh[1024*2048];   // shared_W[0:2048] transposed [N][K], bf16
__device__ __nv_bfloat16 g_Wb_ts[1024*1024];
__device__ __nv_bfloat16 g_Wb_pt[1024*1024];

// ---------------- ptx helpers (arch-generic only) ----------------
__device__ __forceinline__ uint32_t smem_u32(const void* p) {
    return (uint32_t)__cvta_generic_to_shared(p);
}
__device__ __forceinline__ void cpasync16(uint32_t dst, const void* src) {
    uint64_t g = __cvta_generic_to_global(src);
    asm volatile("cp.async.cg.shared.global [%0], [%1], 16;\n" :: "r"(dst), "l"(g));
}
__device__ __forceinline__ void ldsm4(uint32_t* r, uint32_t addr) {
    asm volatile("ldmatrix.sync.aligned.m8n8.x4.shared.b16 {%0,%1,%2,%3}, [%4];\n"
                 : "=r"(r[0]), "=r"(r[1]), "=r"(r[2]), "=r"(r[3]) : "r"(addr));
}
__device__ __forceinline__ void mma_bf16(float* d,
                                         uint32_t a0, uint32_t a1, uint32_t a2, uint32_t a3,
                                         uint32_t b0, uint32_t b1) {
    asm volatile(
        "mma.sync.aligned.m16n8k16.row.col.f32.bf16.bf16.f32 "
        "{%0,%1,%2,%3}, {%4,%5,%6,%7}, {%8,%9}, {%0,%1,%2,%3};\n"
        : "+f"(d[0]), "+f"(d[1]), "+f"(d[2]), "+f"(d[3])
        : "r"(a0), "r"(a1), "r"(a2), "r"(a3), "r"(b0), "r"(b1));
}

#define SWZ128(x) ((x) ^ (((x) >> 3) & 0x70))

__device__ __forceinline__ __nv_bfloat162 pack_bf2(float x, float y) {
    return __floats2bfloat162_rn(x, y);
}
__device__ __forceinline__ float2 unpack_bf2(__nv_bfloat162 v) {
    return __bfloat1622float2(v);
}

// ---------------- helpers ----------------
template<int N>
__device__ __forceinline__ void blockReduceN(float* v, float* sh) {
    int lane = threadIdx.x & 31, wid = threadIdx.x >> 5;
#pragma unroll
    for (int i = 0; i < N; i++) {
        float x = v[i];
#pragma unroll
        for (int o = 16; o; o >>= 1) x += __shfl_xor_sync(0xffffffffu, x, o);
        if (lane == 0) sh[i * 8 + wid] = x;
    }
    __syncthreads();
    if (wid == 0) {
#pragma unroll
        for (int i = 0; i < N; i++) {
            float x = (lane < 8) ? sh[i * 8 + lane] : 0.f;
#pragma unroll
            for (int o = 4; o; o >>= 1) x += __shfl_xor_sync(0xffffffffu, x, o);
            if (lane == 0) sh[i * 8] = x;
        }
    }
    __syncthreads();
#pragma unroll
    for (int i = 0; i < N; i++) v[i] = sh[i * 8];
    __syncthreads();
}

// ---------------- 1. scores ----------------
__global__ void k_scores(const float* __restrict__ pt, const float* __restrict__ aw,
                         const float* __restrict__ ab) {
    int row = blockIdx.x * 8 + (threadIdx.x >> 5);
    int lane = threadIdx.x & 31;
    if (row >= NROWS) return;
    const float4* p = (const float4*)(pt + (size_t)row * DD);
    const float4* w = (const float4*)aw;
    float s = 0.f;
#pragma unroll 4
    for (int i = lane; i < 256; i += 32) {
        float4 a = p[i], b = w[i];
        s += a.x * b.x + a.y * b.y + a.z * b.z + a.w * b.w;
    }
#pragma unroll
    for (int o = 16; o; o >>= 1) s += __shfl_xor_sync(0xffffffffu, s, o);
    if (lane == 0) g_scores[row] = s + ab[0];
}

// ---------------- 2. top-3 per batch ----------------
__global__ void k_topk() {
    int b = blockIdx.x;
    const float* sc = g_scores + b * SS;
    float v[3] = {-1e38f, -1e38f, -1e38f};
    int   id[3] = {-1, -1, -1};
    for (int s = threadIdx.x; s < SS; s += blockDim.x) {
        float x = sc[s];
        if (x > v[0]) { v[2]=v[1]; id[2]=id[1]; v[1]=v[0]; id[1]=id[0]; v[0]=x; id[0]=s; }
        else if (x > v[1]) { v[2]=v[1]; id[2]=id[1]; v[1]=x; id[1]=s; }
        else if (x > v[2]) { v[2]=x; id[2]=s; }
    }
    __shared__ float sv[256 * 3];
    __shared__ int   si[256 * 3];
    for (int j = 0; j < 3; j++) { sv[threadIdx.x*3+j] = v[j]; si[threadIdx.x*3+j] = id[j]; }
    __syncthreads();
    if (threadIdx.x == 0) {
        float bv[3] = {-1e38f, -1e38f, -1e38f};
        int   bi[3] = {-1, -1, -1};
        for (int t = 0; t < 256 * 3; t++) {
            float x = sv[t]; int ix = si[t];
            if (ix < 0) continue;
            for (int j = 0; j < 3; j++) {
                bool better = (x > bv[j]) || (x == bv[j] && (bi[j] < 0 || ix < bi[j]));
                if (better) {
                    for (int q = 2; q > j; q--) { bv[q] = bv[q-1]; bi[q] = bi[q-1]; }
                    bv[j] = x; bi[j] = ix;
                    break;
                }
            }
        }
        for (int j = 0; j < 3; j++) g_aidx[b * 3 + j] = bi[j];
    }
}

// ---------------- 3. translated vectors + spread normalizers ----------------
__global__ void k_translate(const float* __restrict__ pt, const float* __restrict__ cent,
                            const float* __restrict__ ta, const float* __restrict__ tb,
                            const float* __restrict__ pp) {
    int bk = blockIdx.x;
    int b = bk / 3;
    int aidx = g_aidx[bk];
    int t = threadIdx.x;
    __shared__ float a[DD];
    __shared__ float wsm[MMm];
    __shared__ float red[24];
    __shared__ float lowp[4][RRr];
    __shared__ float low[RRr];
    __shared__ float anorm_s;
    const float* arow = pt + ((size_t)b * SS + aidx) * DD;
    for (int i = t; i < DD; i += 256) a[i] = arow[i];
    __syncthreads();
    float v1[1]; v1[0] = 0.f;
    for (int i = t; i < DD; i += 256) v1[0] += a[i] * a[i];
    blockReduceN<1>(v1, red);
    if (t == 0) anorm_s = fmaxf(sqrtf(v1[0]), 1e-6f);
    __syncthreads();
    int wid = t >> 5, lane = t & 31;
    for (int m = wid; m < MMm; m += 8) {
        const float* c = cent + (size_t)m * DD;
        float d = 0.f, cn = 0.f;
        for (int i = lane; i < DD; i += 32) { float cv = c[i]; d += a[i] * cv; cn += cv * cv; }
#pragma unroll
        for (int o = 16; o; o >>= 1) {
            d  += __shfl_xor_sync(0xffffffffu, d, o);
            cn += __shfl_xor_sync(0xffffffffu, cn, o);
        }
        if (lane == 0) wsm[m] = d / (anorm_s * fmaxf(sqrtf(cn), 1e-6f));
    }
    __syncthreads();
    if (t < 32) {
        float x = wsm[t];
        float mx = x;
#pragma unroll
        for (int o = 16; o; o >>= 1) mx = fmaxf(mx, __shfl_xor_sync(0xffffffffu, mx, o));
        float e = expf(x - mx);
        float sm = e;
#pragma unroll
        for (int o = 16; o; o >>= 1) sm += __shfl_xor_sync(0xffffffffu, sm, o);
        wsm[t] = e / sm;
    }
    __syncthreads();
    {
        int r = t & 63, q = t >> 6;
        float acc = 0.f;
        for (int d = q * 256; d < q * 256 + 256; ++d) {
            float wa = 0.f;
#pragma unroll 8
            for (int m = 0; m < MMm; m++) wa += wsm[m] * ta[((size_t)m * DD + d) * RRr + r];
            acc += a[d] * wa;
        }
        lowp[q][r] = acc;
    }
    __syncthreads();
    if (t < 64) low[t] = lowp[0][t] + lowp[1][t] + lowp[2][t] + lowp[3][t];
    __syncthreads();
    for (int d = t; d < DD; d += 256) {
        float acc = 0.f;
        for (int m = 0; m < MMm; m++) {
            const float* tbp = tb + ((size_t)m * DD + d) * RRr;
            float pr = 0.f;
#pragma unroll
            for (int r = 0; r < RRr; r += 4)
                pr += low[r] * tbp[r] + low[r+1] * tbp[r+1] + low[r+2] * tbp[r+2] + low[r+3] * tbp[r+3];
            acc += wsm[m] * pr;
        }
        g_transl[(size_t)bk * DD + d] = acc;
    }
    float ps = pp[aidx];
    float zp[1]; zp[0] = 0.f;
    for (int s = t; s < SS; s += 256) {
        float dd = fabsf(pp[s] - ps);
        if (dd <= 8.0f) zp[0] += expf(-dd * 0.125f);
    }
    blockReduceN<1>(zp, red);
    if (t == 0) { g_Zs[bk] = zp[0]; g_apos[bk] = ps; }
}

// ---------------- 4. fused per-row: update + LN x3 + gate (bf16 tsn/ptn out) -------
__global__ void k_rows(const float* __restrict__ ts, const float* __restrict__ pt,
                       const float* __restrict__ pp, const float* __restrict__ stab,
                       const float* __restrict__ ong, const float* __restrict__ onb,
                       const float* __restrict__ tsg, const float* __restrict__ tsb,
                       const float* __restrict__ ptg, const float* __restrict__ ptb,
                       const float* __restrict__ bsc) {
    __shared__ float sh[24];
    int row = blockIdx.x;
    int b = row >> 12, s = row & 4095;
    int t = threadIdx.x;
    float ps = pp[s];
    float wk[3];
#pragma unroll
    for (int k = 0; k < 3; k++) {
        float d = fabsf(ps - g_apos[b * 3 + k]);
        wk[k] = (d <= 8.0f) ? expf(-d * 0.125f) / g_Zs[b * 3 + k] : 0.f;
    }
    size_t off = (size_t)row * DD + t * 4;
    float4 x = *(const float4*)(ts + off);
#pragma unroll
    for (int k = 0; k < 3; k++) {
        if (wk[k] != 0.f) {
            float4 tr = *(const float4*)(g_transl + (size_t)(b * 3 + k) * DD + t * 4);
            x.x += wk[k] * tr.x; x.y += wk[k] * tr.y; x.z += wk[k] * tr.z; x.w += wk[k] * tr.w;
        }
    }
    float v[3];
    v[0] = x.x + x.y + x.z + x.w;
    v[1] = x.x * x.x + x.y * x.y + x.z * x.z + x.w * x.w;
    blockReduceN<2>(v, sh);
    float mu = v[0] * (1.f / DD);
    float rs = rsqrtf(v[1] * (1.f / DD) - mu * mu + 1e-5f);
    float4 g4 = *(const float4*)(ong + t * 4), b4 = *(const float4*)(onb + t * 4);
    float4 aug;
    aug.x = (x.x - mu) * rs * g4.x + b4.x;
    aug.y = (x.y - mu) * rs * g4.y + b4.y;
    aug.z = (x.z - mu) * rs * g4.z + b4.z;
    aug.w = (x.w - mu) * rs * g4.w + b4.w;
    *(float4*)(g_tsaug + off) = aug;
    v[0] = aug.x + aug.y + aug.z + aug.w;
    v[1] = aug.x * aug.x + aug.y * aug.y + aug.z * aug.z + aug.w * aug.w;
    blockReduceN<2>(v, sh);
    mu = v[0] * (1.f / DD);
    rs = rsqrtf(v[1] * (1.f / DD) - mu * mu + 1e-5f);
    g4 = *(const float4*)(tsg + t * 4); b4 = *(const float4*)(tsb + t * 4);
    float4 tn;
    tn.x = (aug.x - mu) * rs * g4.x + b4.x;
    tn.y = (aug.y - mu) * rs * g4.y + b4.y;
    tn.z = (aug.z - mu) * rs * g4.z + b4.z;
    tn.w = (aug.w - mu) * rs * g4.w + b4.w;
    { __nv_bfloat162* pb = (__nv_bfloat162*)(gb_tsn + off);
      pb[0] = pack_bf2(tn.x, tn.y); pb[1] = pack_bf2(tn.z, tn.w); }
    float4 p = *(const float4*)(pt + off);
    v[0] = p.x + p.y + p.z + p.w;
    v[1] = p.x * p.x + p.y * p.y + p.z * p.z + p.w * p.w;
    blockReduceN<2>(v, sh);
    mu = v[0] * (1.f / DD);
    rs = rsqrtf(v[1] * (1.f / DD) - mu * mu + 1e-5f);
    g4 = *(const float4*)(ptg + t * 4); b4 = *(const float4*)(ptb + t * 4);
    float4 pn;
    pn.x = (p.x - mu) * rs * g4.x + b4.x;
    pn.y = (p.y - mu) * rs * g4.y + b4.y;
    pn.z = (p.z - mu) * rs * g4.z + b4.z;
    pn.w = (p.w - mu) * rs * g4.w + b4.w;
    { __nv_bfloat162* pb = (__nv_bfloat162*)(gb_ptn + off);
      pb[0] = pack_bf2(pn.x, pn.y); pb[1] = pack_bf2(pn.z, pn.w); }
    v[0] = tn.x * pn.x + tn.y * pn.y + tn.z * pn.z + tn.w * pn.w;
    v[1] = tn.x * tn.x + tn.y * tn.y + tn.z * tn.z + tn.w * tn.w;
    v[2] = pn.x * pn.x + pn.y * pn.y + pn.z * pn.z + pn.w * pn.w;
    blockReduceN<3>(v, sh);
    if (t == 0) {
        float cosv = v[0] / (fmaxf(sqrtf(v[1]), 1e-6f) * fmaxf(sqrtf(v[2]), 1e-6f));
        float agree = 0.5f * (1.f + cosv);
        float z = (agree - 0.72f) * 5.0f;
        float focus = 0.2f + 0.8f * expf(-0.5f * z * z);
        float gate = agree * focus * stab[row];
        float blend = 0.35f / (1.f + expf(-bsc[0]));
        g_gate[row] = gate;
        g_lb[row] = blend * gate;
    }
}

// ---------------- weight transpose -> bf16: Wt[n][k] = bf16(W[k][n]) ----------------
__global__ void k_transp(const float* __restrict__ W, __nv_bfloat16* __restrict__ Wt, int K) {
    __shared__ float tile[32][33];
    int k0 = blockIdx.x * 32, n0 = blockIdx.y * 32;
    int tx = threadIdx.x, ty = threadIdx.y;
    for (int i = ty; i < 32; i += 8)
        tile[i][tx] = W[(size_t)(k0 + i) * 1024 + n0 + tx];
    __syncthreads();
    for (int i = ty; i < 32; i += 8)
        Wt[(size_t)(n0 + i) * K + k0 + tx] = __float2bfloat16(tile[tx][i]);
}

// ---------------- bf16 mma.sync GEMM, 128x128 tile, K-tile 64, 3-stage pipeline ----
// MODE 0: C = [tsn|ptn] @ Wb_sh^T (+gate row+bias) -> gb_shared (bf16)   (K=2048)
// MODE 1: out = tsaug + lb * (d1 @ Wb_ts^T)                              (K=1024)
// MODE 2: out = basep + lb * (d2 @ Wb_pt^T)                              (K=1024)
// smem: 3 stages x (A 16KB + B 16KB) = 96KB, SW128-swizzled 128B rows (64 bf16).
#define STAGE_BYTES 32768u
#define NSTAGE 3
#define DSM_BYTES (NSTAGE * 32768)

template<int MODE>
__global__ __launch_bounds__(256, 2)
void k_mm(const __nv_bfloat16* __restrict__ Wt,
          const float* __restrict__ swfull,
          const float* __restrict__ bias,
          const float* __restrict__ basep,
          float* __restrict__ Cout) {
    constexpr int KD = (MODE == 0) ? 2048 : 1024;
    constexpr int KT = KD / 64;

    extern __shared__ __align__(1024) char dsm[];
    uint32_t smem = smem_u32(dsm);
    const int bm = blockIdx.y, bn = blockIdx.x;
    const int t = threadIdx.x;
    const int wid = t >> 5, lane = t & 31;
    const int r = lane >> 2, kk = lane & 3;     // C fragment coords
    const int m0 = (wid & 3) * 32;              // warp m origin within tile
    const int n0 = (wid >> 2) * 64;             // warp n origin within tile
    const uint32_t lrow = lane & 15;            // ldmatrix row select
    const uint32_t lkb  = (lane >> 4) << 4;     // ldmatrix 16B column select

    float acc[2][8][4];
#pragma unroll
    for (int i = 0; i < 2; i++)
#pragma unroll
        for (int j = 0; j < 8; j++)
#pragma unroll
            for (int q = 0; q < 4; q++) acc[i][j][q] = 0.f;

    auto issue_tile = [&](int kt) {
        const __nv_bfloat16* asrc; int kc;
        if (MODE == 0) {
            if (kt < 16) { asrc = gb_tsn; kc = kt * 64; }
            else         { asrc = gb_ptn; kc = (kt - 16) * 64; }
        } else {
            asrc = (MODE == 1) ? gb_d1 : gb_d2;
            kc = kt * 64;
        }
        uint32_t aS = smem + (uint32_t)(kt % NSTAGE) * STAGE_BYTES;
        uint32_t bS = aS + 16384u;
#pragma unroll
        for (int p = 0; p < 4; p++) {
            int chunk = t + p * 256;            // 0..1023 (16B chunks)
            int row = chunk >> 3, ci = chunk & 7;
            uint32_t sw = SWZ128((uint32_t)(row * 128 + ci * 16));
            cpasync16(aS + sw, asrc + (size_t)(bm * 128 + row) * 1024 + kc + ci * 8);
            cpasync16(bS + sw, Wt + (size_t)(bn * 128 + row) * KD + kt * 64 + ci * 8);
        }
        asm volatile("cp.async.commit_group;\n" ::: "memory");
    };

    // prologue: 2 stages in flight
    issue_tile(0);
    issue_tile(1);

    for (int kt = 0; kt < KT; ++kt) {
        if (kt < KT - 1) {
            asm volatile("cp.async.wait_group 1;\n" ::: "memory");  // stage kt ready
        } else {
            asm volatile("cp.async.wait_group 0;\n" ::: "memory");  // last tile: flush
        }
        __syncthreads();   // all threads' waits done; stage (kt+2)%3 fully consumed at kt-1
        if (kt + 2 < KT) issue_tile(kt + 2);

        uint32_t aS = smem + (uint32_t)(kt % NSTAGE) * STAGE_BYTES;
        uint32_t bS = aS + 16384u;
#pragma unroll
        for (int ks = 0; ks < 4; ks++) {
            uint32_t kbyte = (uint32_t)ks * 32 + lkb;
            uint32_t af[2][4];
#pragma unroll
            for (int i = 0; i < 2; i++) {
                uint32_t row = (uint32_t)(m0 + i * 16) + lrow;
                uint32_t off = row * 128 + kbyte;
                ldsm4(af[i], aS + SWZ128(off));
            }
            uint32_t bf[8][2];
#pragma unroll
            for (int jj = 0; jj < 4; jj++) {
                uint32_t row = (uint32_t)(n0 + jj * 16) + lrow;
                uint32_t off = row * 128 + kbyte;
                uint32_t mreg[4];
                ldsm4(mreg, bS + SWZ128(off));
                bf[2*jj][0] = mreg[0]; bf[2*jj][1] = mreg[2];
                bf[2*jj+1][0] = mreg[1]; bf[2*jj+1][1] = mreg[3];
            }
#pragma unroll
            for (int i = 0; i < 2; i++)
#pragma unroll
                for (int j = 0; j < 8; j++)
                    mma_bf16(acc[i][j], af[i][0], af[i][1], af[i][2], af[i][3],
                             bf[j][0], bf[j][1]);
        }
        // no trailing sync: next iteration's wait+sync provides the barrier
    }

    // ---------------- epilogue (C fragment: rows r, r+8; cols 2*kk within n-tile) -------
#pragma unroll
    for (int i = 0; i < 2; i++) {
#pragma unroll
        for (int h = 0; h < 2; h++) {
            size_t rg = (size_t)bm * 128 + m0 + i * 16 + r + h * 8;
            if (MODE == 0) {
                float gv = g_gate[rg];
#pragma unroll
                for (int j = 0; j < 8; j++) {
                    int c = bn * 128 + n0 + j * 8 + 2 * kk;
                    float2 w2 = *(const float2*)(swfull + (size_t)2048 * 1024 + c);
                    float2 b2 = *(const float2*)(bias + c);
                    float ox = acc[i][j][h * 2 + 0] + gv * w2.x + b2.x;
                    float oy = acc[i][j][h * 2 + 1] + gv * w2.y + b2.y;
                    *(__nv_bfloat162*)(gb_shared + rg * 1024 + c) = pack_bf2(ox, oy);
                }
            } else {
                float lbv = g_lb[rg];
                const float* bp = (MODE == 1) ? (const float*)g_tsaug : basep;
#pragma unroll
                for (int j = 0; j < 8; j++) {
                    int c = bn * 128 + n0 + j * 8 + 2 * kk;
                    float2 b2 = *(const float2*)(bp + rg * 1024 + c);
                    float2 o;
                    o.x = b2.x + lbv * acc[i][j][h * 2 + 0];
                    o.y = b2.y + lbv * acc[i][j][h * 2 + 1];
                    *(float2*)(Cout + rg * 1024 + c) = o;
                }
            }
        }
    }
}

// ---------------- causal pool (k=3) -> bf16 difference operands ----------------
// thread handles 4 cols (8 bytes bf16); reads 3 sharedbuf rows + tsn + ptn, writes d1,d2.
__global__ void k_pool() {
    size_t idx = (size_t)blockIdx.x * 256 + threadIdx.x;  // 4-col group index
    size_t row = idx >> 8;
    int c4 = (int)(idx & 255) * 4;                        // col start
    int b = (int)(row >> 12), s = (int)(row & 4095);
    size_t bb0 = (size_t)b * SS;
    auto ld4 = [&](const __nv_bfloat16* base, size_t rr) -> float4 {
        const __nv_bfloat162* p = (const __nv_bfloat162*)(base + rr * DD + c4);
        float2 a = unpack_bf2(p[0]), bq = unpack_bf2(p[1]);
        return make_float4(a.x, a.y, bq.x, bq.y);
    };
    float4 v0 = ld4(gb_shared, bb0 + s);
    float4 v1 = ld4(gb_shared, bb0 + (s >= 1 ? s - 1 : 0));
    float4 v2 = ld4(gb_shared, bb0 + (s >= 2 ? s - 2 : 0));
    const float inv3 = 1.f / 3.f;
    float4 pl;
    pl.x = (v0.x + v1.x + v2.x) * inv3;
    pl.y = (v0.y + v1.y + v2.y) * inv3;
    pl.z = (v0.z + v1.z + v2.z) * inv3;
    pl.w = (v0.w + v1.w + v2.w) * inv3;
    float4 tn = ld4(gb_tsn, row);
    float4 pn = ld4(gb_ptn, row);
    __nv_bfloat162* d1 = (__nv_bfloat162*)(gb_d1 + row * DD + c4);
    __nv_bfloat162* d2 = (__nv_bfloat162*)(gb_d2 + row * DD + c4);
    d1[0] = pack_bf2(pl.x - tn.x, pl.y - tn.y);
    d1[1] = pack_bf2(pl.z - tn.z, pl.w - tn.w);
    d2[0] = pack_bf2(pl.x - pn.x, pl.y - pn.y);
    d2[1] = pack_bf2(pl.z - pn.z, pl.w - pn.w);
}

// ---------------- launch ----------------
extern "C" void kernel_launch(void* const* d_in, const int* in_sizes, int n_in,
                              void* d_out, int out_size) {
    const float* pt   = (const float*)d_in[0];
    const float* ts   = (const float*)d_in[1];
    const float* pp   = (const float*)d_in[2];
    const float* cent = (const float*)d_in[3];
    const float* stab = (const float*)d_in[4];
    const float* aw   = (const float*)d_in[5];
    const float* ab   = (const float*)d_in[6];
    const float* ta   = (const float*)d_in[7];
    const float* tb   = (const float*)d_in[8];
    const float* ong  = (const float*)d_in[9];
    const float* onb  = (const float*)d_in[10];
    const float* tsg  = (const float*)d_in[11];
    const float* tsb  = (const float*)d_in[12];
    const float* ptg  = (const float*)d_in[13];
    const float* ptb  = (const float*)d_in[14];
    const float* sw   = (const float*)d_in[15];
    const float* sb   = (const float*)d_in[16];
    const float* tsup = (const float*)d_in[17];
    const float* ptup = (const float*)d_in[18];
    const float* bsc  = (const float*)d_in[19];
    float* out = (float*)d_out;

    cudaFuncSetAttribute(k_mm<0>, cudaFuncAttributeMaxDynamicSharedMemorySize, DSM_BYTES);
    cudaFuncSetAttribute(k_mm<1>, cudaFuncAttributeMaxDynamicSharedMemorySize, DSM_BYTES);
    cudaFuncSetAttribute(k_mm<2>, cudaFuncAttributeMaxDynamicSharedMemorySize, DSM_BYTES);

    __nv_bfloat16* Wb_sh; cudaGetSymbolAddress((void**)&Wb_sh, g_Wb_sh);
    __nv_bfloat16* Wb_ts; cudaGetSymbolAddress((void**)&Wb_ts, g_Wb_ts);
    __nv_bfloat16* Wb_pt; cudaGetSymbolAddress((void**)&Wb_pt, g_Wb_pt);

    k_transp<<<dim3(64, 32), dim3(32, 8)>>>(sw, Wb_sh, 2048);
    k_transp<<<dim3(32, 32), dim3(32, 8)>>>(tsup, Wb_ts, 1024);
    k_transp<<<dim3(32, 32), dim3(32, 8)>>>(ptup, Wb_pt, 1024);

    k_scores<<<NROWS / 8, 256>>>(pt, aw, ab);
    k_topk<<<BB, 256>>>();
    k_translate<<<BB * KKk, 256>>>(pt, cent, ta, tb, pp);
    k_rows<<<NROWS, 256>>>(ts, pt, pp, stab, ong, onb, tsg, tsb, ptg, ptb, bsc);

    dim3 gg(8, 256);
    k_mm<0><<<gg, 256, DSM_BYTES>>>(Wb_sh, sw, sb, nullptr, nullptr);
    k_pool<<<NROWS, 256>>>();
    k_mm<1><<<gg, 256, DSM_BYTES>>>(Wb_ts, nullptr, nullptr, nullptr, out);
    k_mm<2><<<gg, 256, DSM_BYTES>>>(Wb_pt, nullptr, nullptr, pt, out + (size_t)NROWS * DD);
}

// round 17
// speedup vs baseline: 1.0549x; 1.0549x over previous
#include <cuda_runtime.h>
#include <cuda_bf16.h>
#include <math.h>
#include <stdint.h>

// Problem constants
#define BB 8
#define SS 4096
#define DD 1024
#define MMm 32
#define KKk 3
#define RRr 64
#define NROWS 32768           // BB*SS
#define NELEM ((size_t)NROWS*DD)

// ---------------- scratch (static __device__ globals; no allocation) ----------------
__device__ float g_scores[NROWS];
__device__ float g_apos[BB*KKk];
__device__ float g_Zs[BB*KKk];
__device__ float g_transl[BB*KKk*DD];
__device__ float g_gate[NROWS];
__device__ float g_lb[NROWS];
__device__ float g_tsaug[33554432];          // fp32 (mode-1 epilogue base)
__device__ __nv_bfloat16 gb_tsn[33554432];
__device__ __nv_bfloat16 gb_ptn[33554432];
__device__ __nv_bfloat16 gb_shared[33554432];  // mode-0 output (bf16)
__device__ __nv_bfloat16 gb_d1[33554432];      // pooled - tsn
__device__ __nv_bfloat16 gb_d2[33554432];      // pooled - ptn
__device__ __nv_bfloat16 g_Wb_sh[1024*2048];   // shared_W[0:2048]^T [N][K] bf16
__device__ __nv_bfloat16 g_Wb_ts[1024*1024];
__device__ __nv_bfloat16 g_Wb_pt[1024*1024];

// ---------------- ptx helpers (arch-generic only) ----------------
__device__ __forceinline__ uint32_t smem_u32(const void* p) {
    return (uint32_t)__cvta_generic_to_shared(p);
}
__device__ __forceinline__ void cpasync16(uint32_t dst, const void* src) {
    uint64_t g = __cvta_generic_to_global(src);
    asm volatile("cp.async.cg.shared.global [%0], [%1], 16;\n" :: "r"(dst), "l"(g));
}
__device__ __forceinline__ void ldsm4(uint32_t* r, uint32_t addr) {
    asm volatile("ldmatrix.sync.aligned.m8n8.x4.shared.b16 {%0,%1,%2,%3}, [%4];\n"
                 : "=r"(r[0]), "=r"(r[1]), "=r"(r[2]), "=r"(r[3]) : "r"(addr));
}
__device__ __forceinline__ void mma_bf16(float* d,
                                         uint32_t a0, uint32_t a1, uint32_t a2, uint32_t a3,
                                         uint32_t b0, uint32_t b1) {
    asm volatile(
        "mma.sync.aligned.m16n8k16.row.col.f32.bf16.bf16.f32 "
        "{%0,%1,%2,%3}, {%4,%5,%6,%7}, {%8,%9}, {%0,%1,%2,%3};\n"
        : "+f"(d[0]), "+f"(d[1]), "+f"(d[2]), "+f"(d[3])
        : "r"(a0), "r"(a1), "r"(a2), "r"(a3), "r"(b0), "r"(b1));
}

#define SWZ128(x) ((x) ^ (((x) >> 3) & 0x70))

__device__ __forceinline__ __nv_bfloat162 pack_bf2(float x, float y) {
    return __floats2bfloat162_rn(x, y);
}
__device__ __forceinline__ float2 unpack_bf2(__nv_bfloat162 v) {
    return __bfloat1622float2(v);
}

// ---------------- helpers ----------------
template<int N>
__device__ __forceinline__ void blockReduceN(float* v, float* sh) {
    int lane = threadIdx.x & 31, wid = threadIdx.x >> 5;
#pragma unroll
    for (int i = 0; i < N; i++) {
        float x = v[i];
#pragma unroll
        for (int o = 16; o; o >>= 1) x += __shfl_xor_sync(0xffffffffu, x, o);
        if (lane == 0) sh[i * 8 + wid] = x;
    }
    __syncthreads();
    if (wid == 0) {
#pragma unroll
        for (int i = 0; i < N; i++) {
            float x = (lane < 8) ? sh[i * 8 + lane] : 0.f;
#pragma unroll
            for (int o = 4; o; o >>= 1) x += __shfl_xor_sync(0xffffffffu, x, o);
            if (lane == 0) sh[i * 8] = x;
        }
    }
    __syncthreads();
#pragma unroll
    for (int i = 0; i < N; i++) v[i] = sh[i * 8];
    __syncthreads();
}

// ---------------- launch 0: fused init = 3 weight transposes + scores ----------------
// blocks [0,2048): Wsh^T; [2048,3072): Wts^T; [3072,4096): Wpt^T; [4096,8192): scores
__global__ void k_init(const float* __restrict__ sw, const float* __restrict__ tsup,
                       const float* __restrict__ ptup, const float* __restrict__ pt,
                       const float* __restrict__ aw, const float* __restrict__ ab) {
    int bid = blockIdx.x;
    if (bid < 4096) {
        const float* W; __nv_bfloat16* Wt; int K, i;
        if (bid < 2048)      { W = sw;   Wt = g_Wb_sh; K = 2048; i = bid; }
        else if (bid < 3072) { W = tsup; Wt = g_Wb_ts; K = 1024; i = bid - 2048; }
        else                 { W = ptup; Wt = g_Wb_pt; K = 1024; i = bid - 3072; }
        int nb = K / 32;
        int k0 = (i % nb) * 32, n0 = (i / nb) * 32;
        __shared__ float tile[32][33];
        int tx = threadIdx.x & 31, ty = threadIdx.x >> 5;
        for (int q = ty; q < 32; q += 8)
            tile[q][tx] = W[(size_t)(k0 + q) * 1024 + n0 + tx];
        __syncthreads();
        for (int q = ty; q < 32; q += 8)
            Wt[(size_t)(n0 + q) * K + k0 + tx] = __float2bfloat16(tile[tx][q]);
    } else {
        int row = (bid - 4096) * 8 + (threadIdx.x >> 5);
        int lane = threadIdx.x & 31;
        const float4* p = (const float4*)(pt + (size_t)row * DD);
        const float4* w = (const float4*)aw;
        float s = 0.f;
#pragma unroll 4
        for (int i = lane; i < 256; i += 32) {
            float4 a = p[i], b = w[i];
            s += a.x * b.x + a.y * b.y + a.z * b.z + a.w * b.w;
        }
#pragma unroll
        for (int o = 16; o; o >>= 1) s += __shfl_xor_sync(0xffffffffu, s, o);
        if (lane == 0) g_scores[row] = s + ab[0];
    }
}

// ---------------- launch 1: fused topk (per-block rescan) + translate ----------------
__global__ void k_tt(const float* __restrict__ pt, const float* __restrict__ cent,
                     const float* __restrict__ ta, const float* __restrict__ tb,
                     const float* __restrict__ pp) {
    int bk = blockIdx.x;
    int b = bk / 3, kwant = bk % 3;
    int t = threadIdx.x;
    __shared__ float sv[256 * 3];
    __shared__ int   si[256 * 3];
    __shared__ int   aidx_s;
    // --- top-3 rescan for batch b ---
    {
        const float* sc = g_scores + b * SS;
        float v[3] = {-1e38f, -1e38f, -1e38f};
        int   id[3] = {-1, -1, -1};
        for (int s = t; s < SS; s += 256) {
            float x = sc[s];
            if (x > v[0]) { v[2]=v[1]; id[2]=id[1]; v[1]=v[0]; id[1]=id[0]; v[0]=x; id[0]=s; }
            else if (x > v[1]) { v[2]=v[1]; id[2]=id[1]; v[1]=x; id[1]=s; }
            else if (x > v[2]) { v[2]=x; id[2]=s; }
        }
        for (int j = 0; j < 3; j++) { sv[t*3+j] = v[j]; si[t*3+j] = id[j]; }
        __syncthreads();
        if (t == 0) {
            float bv[3] = {-1e38f, -1e38f, -1e38f};
            int   bi[3] = {-1, -1, -1};
            for (int q = 0; q < 256 * 3; q++) {
                float x = sv[q]; int ix = si[q];
                if (ix < 0) continue;
                for (int j = 0; j < 3; j++) {
                    bool better = (x > bv[j]) || (x == bv[j] && (bi[j] < 0 || ix < bi[j]));
                    if (better) {
                        for (int q2 = 2; q2 > j; q2--) { bv[q2] = bv[q2-1]; bi[q2] = bi[q2-1]; }
                        bv[j] = x; bi[j] = ix;
                        break;
                    }
                }
            }
            aidx_s = bi[kwant];
        }
        __syncthreads();
    }
    int aidx = aidx_s;
    // --- translate ---
    __shared__ float a[DD];
    __shared__ float wsm[MMm];
    __shared__ float red[24];
    __shared__ float lowp[4][RRr];
    __shared__ float low[RRr];
    __shared__ float anorm_s;
    const float* arow = pt + ((size_t)b * SS + aidx) * DD;
    for (int i = t; i < DD; i += 256) a[i] = arow[i];
    __syncthreads();
    float v1[1]; v1[0] = 0.f;
    for (int i = t; i < DD; i += 256) v1[0] += a[i] * a[i];
    blockReduceN<1>(v1, red);
    if (t == 0) anorm_s = fmaxf(sqrtf(v1[0]), 1e-6f);
    __syncthreads();
    int wid = t >> 5, lane = t & 31;
    for (int m = wid; m < MMm; m += 8) {
        const float* c = cent + (size_t)m * DD;
        float d = 0.f, cn = 0.f;
        for (int i = lane; i < DD; i += 32) { float cv = c[i]; d += a[i] * cv; cn += cv * cv; }
#pragma unroll
        for (int o = 16; o; o >>= 1) {
            d  += __shfl_xor_sync(0xffffffffu, d, o);
            cn += __shfl_xor_sync(0xffffffffu, cn, o);
        }
        if (lane == 0) wsm[m] = d / (anorm_s * fmaxf(sqrtf(cn), 1e-6f));
    }
    __syncthreads();
    if (t < 32) {
        float x = wsm[t];
        float mx = x;
#pragma unroll
        for (int o = 16; o; o >>= 1) mx = fmaxf(mx, __shfl_xor_sync(0xffffffffu, mx, o));
        float e = expf(x - mx);
        float sm = e;
#pragma unroll
        for (int o = 16; o; o >>= 1) sm += __shfl_xor_sync(0xffffffffu, sm, o);
        wsm[t] = e / sm;
    }
    __syncthreads();
    {
        int r = t & 63, q = t >> 6;
        float acc = 0.f;
        for (int d = q * 256; d < q * 256 + 256; ++d) {
            float wa = 0.f;
#pragma unroll 8
            for (int m = 0; m < MMm; m++) wa += wsm[m] * ta[((size_t)m * DD + d) * RRr + r];
            acc += a[d] * wa;
        }
        lowp[q][r] = acc;
    }
    __syncthreads();
    if (t < 64) low[t] = lowp[0][t] + lowp[1][t] + lowp[2][t] + lowp[3][t];
    __syncthreads();
    for (int d = t; d < DD; d += 256) {
        float acc = 0.f;
        for (int m = 0; m < MMm; m++) {
            const float* tbp = tb + ((size_t)m * DD + d) * RRr;
            float pr = 0.f;
#pragma unroll
            for (int r = 0; r < RRr; r += 4)
                pr += low[r] * tbp[r] + low[r+1] * tbp[r+1] + low[r+2] * tbp[r+2] + low[r+3] * tbp[r+3];
            acc += wsm[m] * pr;
        }
        g_transl[(size_t)bk * DD + d] = acc;
    }
    float ps = pp[aidx];
    float zp[1]; zp[0] = 0.f;
    for (int s = t; s < SS; s += 256) {
        float dd = fabsf(pp[s] - ps);
        if (dd <= 8.0f) zp[0] += expf(-dd * 0.125f);
    }
    blockReduceN<1>(zp, red);
    if (t == 0) { g_Zs[bk] = zp[0]; g_apos[bk] = ps; }
}

// ---------------- launch 2: fused per-row update + LN x3 + gate ----------------
__global__ void k_rows(const float* __restrict__ ts, const float* __restrict__ pt,
                       const float* __restrict__ pp, const float* __restrict__ stab,
                       const float* __restrict__ ong, const float* __restrict__ onb,
                       const float* __restrict__ tsg, const float* __restrict__ tsb,
                       const float* __restrict__ ptg, const float* __restrict__ ptb,
                       const float* __restrict__ bsc) {
    __shared__ float sh[24];
    int row = blockIdx.x;
    int b = row >> 12, s = row & 4095;
    int t = threadIdx.x;
    float ps = pp[s];
    float wk[3];
#pragma unroll
    for (int k = 0; k < 3; k++) {
        float d = fabsf(ps - g_apos[b * 3 + k]);
        wk[k] = (d <= 8.0f) ? expf(-d * 0.125f) / g_Zs[b * 3 + k] : 0.f;
    }
    size_t off = (size_t)row * DD + t * 4;
    float4 x = *(const float4*)(ts + off);
#pragma unroll
    for (int k = 0; k < 3; k++) {
        if (wk[k] != 0.f) {
            float4 tr = *(const float4*)(g_transl + (size_t)(b * 3 + k) * DD + t * 4);
            x.x += wk[k] * tr.x; x.y += wk[k] * tr.y; x.z += wk[k] * tr.z; x.w += wk[k] * tr.w;
        }
    }
    float v[3];
    v[0] = x.x + x.y + x.z + x.w;
    v[1] = x.x * x.x + x.y * x.y + x.z * x.z + x.w * x.w;
    blockReduceN<2>(v, sh);
    float mu = v[0] * (1.f / DD);
    float rs = rsqrtf(v[1] * (1.f / DD) - mu * mu + 1e-5f);
    float4 g4 = *(const float4*)(ong + t * 4), b4 = *(const float4*)(onb + t * 4);
    float4 aug;
    aug.x = (x.x - mu) * rs * g4.x + b4.x;
    aug.y = (x.y - mu) * rs * g4.y + b4.y;
    aug.z = (x.z - mu) * rs * g4.z + b4.z;
    aug.w = (x.w - mu) * rs * g4.w + b4.w;
    *(float4*)(g_tsaug + off) = aug;
    v[0] = aug.x + aug.y + aug.z + aug.w;
    v[1] = aug.x * aug.x + aug.y * aug.y + aug.z * aug.z + aug.w * aug.w;
    blockReduceN<2>(v, sh);
    mu = v[0] * (1.f / DD);
    rs = rsqrtf(v[1] * (1.f / DD) - mu * mu + 1e-5f);
    g4 = *(const float4*)(tsg + t * 4); b4 = *(const float4*)(tsb + t * 4);
    float4 tn;
    tn.x = (aug.x - mu) * rs * g4.x + b4.x;
    tn.y = (aug.y - mu) * rs * g4.y + b4.y;
    tn.z = (aug.z - mu) * rs * g4.z + b4.z;
    tn.w = (aug.w - mu) * rs * g4.w + b4.w;
    { __nv_bfloat162* pb = (__nv_bfloat162*)(gb_tsn + off);
      pb[0] = pack_bf2(tn.x, tn.y); pb[1] = pack_bf2(tn.z, tn.w); }
    float4 p = *(const float4*)(pt + off);
    v[0] = p.x + p.y + p.z + p.w;
    v[1] = p.x * p.x + p.y * p.y + p.z * p.z + p.w * p.w;
    blockReduceN<2>(v, sh);
    mu = v[0] * (1.f / DD);
    rs = rsqrtf(v[1] * (1.f / DD) - mu * mu + 1e-5f);
    g4 = *(const float4*)(ptg + t * 4); b4 = *(const float4*)(ptb + t * 4);
    float4 pn;
    pn.x = (p.x - mu) * rs * g4.x + b4.x;
    pn.y = (p.y - mu) * rs * g4.y + b4.y;
    pn.z = (p.z - mu) * rs * g4.z + b4.z;
    pn.w = (p.w - mu) * rs * g4.w + b4.w;
    { __nv_bfloat162* pb = (__nv_bfloat162*)(gb_ptn + off);
      pb[0] = pack_bf2(pn.x, pn.y); pb[1] = pack_bf2(pn.z, pn.w); }
    v[0] = tn.x * pn.x + tn.y * pn.y + tn.z * pn.z + tn.w * pn.w;
    v[1] = tn.x * tn.x + tn.y * tn.y + tn.z * tn.z + tn.w * tn.w;
    v[2] = pn.x * pn.x + pn.y * pn.y + pn.z * pn.z + pn.w * pn.w;
    blockReduceN<3>(v, sh);
    if (t == 0) {
        float cosv = v[0] / (fmaxf(sqrtf(v[1]), 1e-6f) * fmaxf(sqrtf(v[2]), 1e-6f));
        float agree = 0.5f * (1.f + cosv);
        float z = (agree - 0.72f) * 5.0f;
        float focus = 0.2f + 0.8f * expf(-0.5f * z * z);
        float gate = agree * focus * stab[row];
        float blend = 0.35f / (1.f + expf(-bsc[0]));
        g_gate[row] = gate;
        g_lb[row] = blend * gate;
    }
}

// ---------------- bf16 mma.sync GEMM core (shared by mmA / mmB) ----------------
#define STAGE_BYTES 32768u
#define NSTAGE 3
#define DSM_BYTES (NSTAGE * 32768)

// launch 3: MODE 0  C = [tsn|ptn] @ Wb_sh^T (+gate row+bias) -> gb_shared   (K=2048)
__global__ __launch_bounds__(256, 2)
void k_mmA(const float* __restrict__ swfull, const float* __restrict__ bias) {
    constexpr int KD = 2048;
    constexpr int KT = KD / 64;
    extern __shared__ __align__(1024) char dsm[];
    uint32_t smem = smem_u32(dsm);
    const int bm = blockIdx.y, bn = blockIdx.x;
    const int t = threadIdx.x;
    const int wid = t >> 5, lane = t & 31;
    const int r = lane >> 2, kk = lane & 3;
    const int m0 = (wid & 3) * 32;
    const int n0 = (wid >> 2) * 64;
    const uint32_t lrow = lane & 15;
    const uint32_t lkb  = (lane >> 4) << 4;

    float acc[2][8][4];
#pragma unroll
    for (int i = 0; i < 2; i++)
#pragma unroll
        for (int j = 0; j < 8; j++)
#pragma unroll
            for (int q = 0; q < 4; q++) acc[i][j][q] = 0.f;

    auto issue_tile = [&](int kt) {
        const __nv_bfloat16* asrc; int kc;
        if (kt < 16) { asrc = gb_tsn; kc = kt * 64; }
        else         { asrc = gb_ptn; kc = (kt - 16) * 64; }
        uint32_t aS = smem + (uint32_t)(kt % NSTAGE) * STAGE_BYTES;
        uint32_t bS = aS + 16384u;
#pragma unroll
        for (int p = 0; p < 4; p++) {
            int chunk = t + p * 256;
            int row = chunk >> 3, ci = chunk & 7;
            uint32_t sw = SWZ128((uint32_t)(row * 128 + ci * 16));
            cpasync16(aS + sw, asrc + (size_t)(bm * 128 + row) * 1024 + kc + ci * 8);
            cpasync16(bS + sw, g_Wb_sh + (size_t)(bn * 128 + row) * KD + kt * 64 + ci * 8);
        }
        asm volatile("cp.async.commit_group;\n" ::: "memory");
    };

    issue_tile(0);
    issue_tile(1);
    for (int kt = 0; kt < KT; ++kt) {
        if (kt < KT - 1) asm volatile("cp.async.wait_group 1;\n" ::: "memory");
        else             asm volatile("cp.async.wait_group 0;\n" ::: "memory");
        __syncthreads();
        if (kt + 2 < KT) issue_tile(kt + 2);
        uint32_t aS = smem + (uint32_t)(kt % NSTAGE) * STAGE_BYTES;
        uint32_t bS = aS + 16384u;
#pragma unroll
        for (int ks = 0; ks < 4; ks++) {
            uint32_t kbyte = (uint32_t)ks * 32 + lkb;
            uint32_t af[2][4];
#pragma unroll
            for (int i = 0; i < 2; i++) {
                uint32_t row = (uint32_t)(m0 + i * 16) + lrow;
                ldsm4(af[i], aS + SWZ128(row * 128 + kbyte));
            }
            uint32_t bf[8][2];
#pragma unroll
            for (int jj = 0; jj < 4; jj++) {
                uint32_t row = (uint32_t)(n0 + jj * 16) + lrow;
                uint32_t mreg[4];
                ldsm4(mreg, bS + SWZ128(row * 128 + kbyte));
                bf[2*jj][0] = mreg[0]; bf[2*jj][1] = mreg[2];
                bf[2*jj+1][0] = mreg[1]; bf[2*jj+1][1] = mreg[3];
            }
#pragma unroll
            for (int i = 0; i < 2; i++)
#pragma unroll
                for (int j = 0; j < 8; j++)
                    mma_bf16(acc[i][j], af[i][0], af[i][1], af[i][2], af[i][3],
                             bf[j][0], bf[j][1]);
        }
    }
#pragma unroll
    for (int i = 0; i < 2; i++)
#pragma unroll
        for (int h = 0; h < 2; h++) {
            size_t rg = (size_t)bm * 128 + m0 + i * 16 + r + h * 8;
            float gv = g_gate[rg];
#pragma unroll
            for (int j = 0; j < 8; j++) {
                int c = bn * 128 + n0 + j * 8 + 2 * kk;
                float2 w2 = *(const float2*)(swfull + (size_t)2048 * 1024 + c);
                float2 b2 = *(const float2*)(bias + c);
                float ox = acc[i][j][h * 2 + 0] + gv * w2.x + b2.x;
                float oy = acc[i][j][h * 2 + 1] + gv * w2.y + b2.y;
                *(__nv_bfloat162*)(gb_shared + rg * 1024 + c) = pack_bf2(ox, oy);
            }
        }
}

// launch 5: MODE 1/2 merged via blockIdx.z
//  z=0: out_ts = tsaug + lb*(d1 @ Wb_ts^T);  z=1: out_pt = pt + lb*(d2 @ Wb_pt^T)
__global__ __launch_bounds__(256, 2)
void k_mmB(const float* __restrict__ ptbase, float* __restrict__ outbase) {
    constexpr int KD = 1024;
    constexpr int KT = KD / 64;
    extern __shared__ __align__(1024) char dsm[];
    uint32_t smem = smem_u32(dsm);
    const int bm = blockIdx.y, bn = blockIdx.x, z = blockIdx.z;
    const __nv_bfloat16* __restrict__ asrc0 = z ? gb_d2 : gb_d1;
    const __nv_bfloat16* __restrict__ Wt    = z ? g_Wb_pt : g_Wb_ts;
    const float* __restrict__ basep = z ? ptbase : (const float*)g_tsaug;
    float* __restrict__ Cout = outbase + (size_t)z * NELEM;
    const int t = threadIdx.x;
    const int wid = t >> 5, lane = t & 31;
    const int r = lane >> 2, kk = lane & 3;
    const int m0 = (wid & 3) * 32;
    const int n0 = (wid >> 2) * 64;
    const uint32_t lrow = lane & 15;
    const uint32_t lkb  = (lane >> 4) << 4;

    float acc[2][8][4];
#pragma unroll
    for (int i = 0; i < 2; i++)
#pragma unroll
        for (int j = 0; j < 8; j++)
#pragma unroll
            for (int q = 0; q < 4; q++) acc[i][j][q] = 0.f;

    auto issue_tile = [&](int kt) {
        uint32_t aS = smem + (uint32_t)(kt % NSTAGE) * STAGE_BYTES;
        uint32_t bS = aS + 16384u;
#pragma unroll
        for (int p = 0; p < 4; p++) {
            int chunk = t + p * 256;
            int row = chunk >> 3, ci = chunk & 7;
            uint32_t sw = SWZ128((uint32_t)(row * 128 + ci * 16));
            cpasync16(aS + sw, asrc0 + (size_t)(bm * 128 + row) * 1024 + kt * 64 + ci * 8);
            cpasync16(bS + sw, Wt + (size_t)(bn * 128 + row) * KD + kt * 64 + ci * 8);
        }
        asm volatile("cp.async.commit_group;\n" ::: "memory");
    };

    issue_tile(0);
    issue_tile(1);
    for (int kt = 0; kt < KT; ++kt) {
        if (kt < KT - 1) asm volatile("cp.async.wait_group 1;\n" ::: "memory");
        else             asm volatile("cp.async.wait_group 0;\n" ::: "memory");
        __syncthreads();
        if (kt + 2 < KT) issue_tile(kt + 2);
        uint32_t aS = smem + (uint32_t)(kt % NSTAGE) * STAGE_BYTES;
        uint32_t bS = aS + 16384u;
#pragma unroll
        for (int ks = 0; ks < 4; ks++) {
            uint32_t kbyte = (uint32_t)ks * 32 + lkb;
            uint32_t af[2][4];
#pragma unroll
            for (int i = 0; i < 2; i++) {
                uint32_t row = (uint32_t)(m0 + i * 16) + lrow;
                ldsm4(af[i], aS + SWZ128(row * 128 + kbyte));
            }
            uint32_t bf[8][2];
#pragma unroll
            for (int jj = 0; jj < 4; jj++) {
                uint32_t row = (uint32_t)(n0 + jj * 16) + lrow;
                uint32_t mreg[4];
                ldsm4(mreg, bS + SWZ128(row * 128 + kbyte));
                bf[2*jj][0] = mreg[0]; bf[2*jj][1] = mreg[2];
                bf[2*jj+1][0] = mreg[1]; bf[2*jj+1][1] = mreg[3];
            }
#pragma unroll
            for (int i = 0; i < 2; i++)
#pragma unroll
                for (int j = 0; j < 8; j++)
                    mma_bf16(acc[i][j], af[i][0], af[i][1], af[i][2], af[i][3],
                             bf[j][0], bf[j][1]);
        }
    }
#pragma unroll
    for (int i = 0; i < 2; i++)
#pragma unroll
        for (int h = 0; h < 2; h++) {
            size_t rg = (size_t)bm * 128 + m0 + i * 16 + r + h * 8;
            float lbv = g_lb[rg];
#pragma unroll
            for (int j = 0; j < 8; j++) {
                int c = bn * 128 + n0 + j * 8 + 2 * kk;
                float2 b2 = *(const float2*)(basep + rg * 1024 + c);
                float2 o;
                o.x = b2.x + lbv * acc[i][j][h * 2 + 0];
                o.y = b2.y + lbv * acc[i][j][h * 2 + 1];
                *(float2*)(Cout + rg * 1024 + c) = o;
            }
        }
}

// ---------------- launch 4: causal pool (k=3) -> bf16 difference operands -------
__global__ void k_pool() {
    size_t idx = (size_t)blockIdx.x * 256 + threadIdx.x;
    size_t row = idx >> 8;
    int c4 = (int)(idx & 255) * 4;
    int b = (int)(row >> 12), s = (int)(row & 4095);
    size_t bb0 = (size_t)b * SS;
    auto ld4 = [&](const __nv_bfloat16* base, size_t rr) -> float4 {
        const __nv_bfloat162* p = (const __nv_bfloat162*)(base + rr * DD + c4);
        float2 a = unpack_bf2(p[0]), bq = unpack_bf2(p[1]);
        return make_float4(a.x, a.y, bq.x, bq.y);
    };
    float4 v0 = ld4(gb_shared, bb0 + s);
    float4 v1 = ld4(gb_shared, bb0 + (s >= 1 ? s - 1 : 0));
    float4 v2 = ld4(gb_shared, bb0 + (s >= 2 ? s - 2 : 0));
    const float inv3 = 1.f / 3.f;
    float4 pl;
    pl.x = (v0.x + v1.x + v2.x) * inv3;
    pl.y = (v0.y + v1.y + v2.y) * inv3;
    pl.z = (v0.z + v1.z + v2.z) * inv3;
    pl.w = (v0.w + v1.w + v2.w) * inv3;
    float4 tn = ld4(gb_tsn, row);
    float4 pn = ld4(gb_ptn, row);
    __nv_bfloat162* d1 = (__nv_bfloat162*)(gb_d1 + row * DD + c4);
    __nv_bfloat162* d2 = (__nv_bfloat162*)(gb_d2 + row * DD + c4);
    d1[0] = pack_bf2(pl.x - tn.x, pl.y - tn.y);
    d1[1] = pack_bf2(pl.z - tn.z, pl.w - tn.w);
    d2[0] = pack_bf2(pl.x - pn.x, pl.y - pn.y);
    d2[1] = pack_bf2(pl.z - pn.z, pl.w - pn.w);
}

// ---------------- launch ----------------
extern "C" void kernel_launch(void* const* d_in, const int* in_sizes, int n_in,
                              void* d_out, int out_size) {
    const float* pt   = (const float*)d_in[0];
    const float* ts   = (const float*)d_in[1];
    const float* pp   = (const float*)d_in[2];
    const float* cent = (const float*)d_in[3];
    const float* stab = (const float*)d_in[4];
    const float* aw   = (const float*)d_in[5];
    const float* ab   = (const float*)d_in[6];
    const float* ta   = (const float*)d_in[7];
    const float* tb   = (const float*)d_in[8];
    const float* ong  = (const float*)d_in[9];
    const float* onb  = (const float*)d_in[10];
    const float* tsg  = (const float*)d_in[11];
    const float* tsb  = (const float*)d_in[12];
    const float* ptg  = (const float*)d_in[13];
    const float* ptb  = (const float*)d_in[14];
    const float* sw   = (const float*)d_in[15];
    const float* sb   = (const float*)d_in[16];
    const float* tsup = (const float*)d_in[17];
    const float* ptup = (const float*)d_in[18];
    const float* bsc  = (const float*)d_in[19];
    float* out = (float*)d_out;

    cudaFuncSetAttribute(k_mmA, cudaFuncAttributeMaxDynamicSharedMemorySize, DSM_BYTES);
    cudaFuncSetAttribute(k_mmB, cudaFuncAttributeMaxDynamicSharedMemorySize, DSM_BYTES);

    // launch 0: transposes + scores
    k_init<<<8192, 256>>>(sw, tsup, ptup, pt, aw, ab);
    // launch 1: topk + translate
    k_tt<<<BB * KKk, 256>>>(pt, cent, ta, tb, pp);
    // launch 2: rows
    k_rows<<<NROWS, 256>>>(ts, pt, pp, stab, ong, onb, tsg, tsb, ptg, ptb, bsc);
    // launch 3 (profiled slot): big GEMM
    k_mmA<<<dim3(8, 256), 256, DSM_BYTES>>>(sw, sb);
    // launch 4: pool
    k_pool<<<NROWS, 256>>>();
    // launch 5: both output GEMMs merged
    k_mmB<<<dim3(8, 256, 2), 256, DSM_BYTES>>>(pt, out);
}